// round 4
// baseline (speedup 1.0000x reference)
#include <cuda_runtime.h>
#include <cstdint>

#define NN 50000
#define EE 800000
#define DD 256
#define LL 3
#define GG 512

// ---------------- scratch (no allocations allowed) ----------------
__device__ float g_agg[NN * DD];          // 51.2 MB
__device__ float g_t[NN * DD];            // 51.2 MB
__device__ int   g_deg[NN];
__device__ int   g_cursor[NN];
__device__ int   g_rowstart[NN + 1];
__device__ int   g_esrc[EE];
__device__ int   g_gstart[GG + 1];

// ---------------- CSR build ----------------
__global__ void zero_deg_kernel() {
    int i = blockIdx.x * blockDim.x + threadIdx.x;
    if (i < NN) g_deg[i] = 0;
}

__global__ void count_kernel(const int* __restrict__ ei) {
    int e = blockIdx.x * blockDim.x + threadIdx.x;
    if (e < EE) atomicAdd(&g_deg[ei[EE + e]], 1);
}

// single-block exclusive scan of g_deg -> g_rowstart (N=50000, 1024 threads)
__global__ void scan_kernel() {
    __shared__ int partials[1024];
    const int n = NN;
    int tid = threadIdx.x;
    int chunk = (n + 1023) / 1024;
    int beg = tid * chunk;
    int end = beg + chunk; if (end > n) end = n;
    int sum = 0;
    for (int i = beg; i < end; i++) sum += g_deg[i];
    partials[tid] = sum;
    __syncthreads();
    // Hillis-Steele inclusive scan
    for (int off = 1; off < 1024; off <<= 1) {
        int v = 0;
        if (tid >= off) v = partials[tid - off];
        __syncthreads();
        partials[tid] += v;
        __syncthreads();
    }
    int run = (tid == 0) ? 0 : partials[tid - 1];
    for (int i = beg; i < end; i++) {
        g_rowstart[i] = run;
        run += g_deg[i];
    }
    if (tid == 0) g_rowstart[n] = EE;
}

__global__ void copy_cursor_kernel() {
    int i = blockIdx.x * blockDim.x + threadIdx.x;
    if (i < NN) g_cursor[i] = g_rowstart[i];
}

__global__ void fill_kernel(const int* __restrict__ ei) {
    int e = blockIdx.x * blockDim.x + threadIdx.x;
    if (e < EE) {
        int dst = ei[EE + e];
        int pos = atomicAdd(&g_cursor[dst], 1);
        g_esrc[pos] = ei[e];
    }
}

// ---------------- aggregation: agg[n] = h[n] + sum_{j->n} h[j] ----------------
// warp per node, each lane owns 8 feature floats (2 x float4)
__global__ __launch_bounds__(256) void aggregate_kernel(
    const float* __restrict__ h, int hstride)
{
    int node = (blockIdx.x * blockDim.x + threadIdx.x) >> 5;
    if (node >= NN) return;
    int lane = threadIdx.x & 31;
    int beg = g_rowstart[node];
    int end = g_rowstart[node + 1];
    int d0 = lane * 4;
    int d1 = 128 + lane * 4;
    float4 acc0 = make_float4(0.f, 0.f, 0.f, 0.f);
    float4 acc1 = make_float4(0.f, 0.f, 0.f, 0.f);
    for (int e = beg; e < end; e++) {
        int s = __ldg(&g_esrc[e]);
        const float* hs = h + (long)s * hstride;
        float4 a = *(const float4*)(hs + d0);
        float4 b = *(const float4*)(hs + d1);
        acc0.x += a.x; acc0.y += a.y; acc0.z += a.z; acc0.w += a.w;
        acc1.x += b.x; acc1.y += b.y; acc1.z += b.z; acc1.w += b.w;
    }
    const float* hn = h + (long)node * hstride;
    float4 a = *(const float4*)(hn + d0);
    float4 b = *(const float4*)(hn + d1);
    float* ao = g_agg + (long)node * DD;
    *(float4*)(ao + d0) = make_float4(acc0.x + a.x, acc0.y + a.y, acc0.z + a.z, acc0.w + a.w);
    *(float4*)(ao + d1) = make_float4(acc1.x + b.x, acc1.y + b.y, acc1.z + b.z, acc1.w + b.w);
}

// ---------------- GEMM + bias + relu: C = relu(A @ W + b) ----------------
// A: M x 256 (row stride lda), W: 256 x 256 row-major, C: M x 256 (row stride ldc)
// block = 256 threads, tile 64x64, K-tile 32, 4x4 per thread
__global__ __launch_bounds__(256) void gemm_bias_relu(
    const float* __restrict__ A, int lda,
    const float* __restrict__ W,
    const float* __restrict__ bias,
    float* __restrict__ C, int ldc, int M)
{
    __shared__ float As[64][33];
    __shared__ float Bs[32][68];

    int tid = threadIdx.x;
    int tx = tid & 15;       // 0..15 -> col group
    int ty = tid >> 4;       // 0..15 -> row group
    int rowBase = blockIdx.x * 64;
    int colBase = blockIdx.y * 64;

    float acc[4][4];
#pragma unroll
    for (int i = 0; i < 4; i++)
#pragma unroll
        for (int j = 0; j < 4; j++) acc[i][j] = 0.f;

    int a_m = tid >> 5;      // 0..7 (+ i*8)
    int a_k = tid & 31;
    int b_k = tid >> 6;      // 0..3 (+ i*4)
    int b_n = tid & 63;

    for (int k0 = 0; k0 < 256; k0 += 32) {
#pragma unroll
        for (int i = 0; i < 8; i++) {
            int m = a_m + i * 8;
            int gr = rowBase + m;
            float v = 0.f;
            if (gr < M) v = A[(long)gr * lda + k0 + a_k];
            As[m][a_k] = v;
        }
#pragma unroll
        for (int i = 0; i < 8; i++) {
            int k = b_k + i * 4;
            Bs[k][b_n] = W[(k0 + k) * 256 + colBase + b_n];
        }
        __syncthreads();
#pragma unroll
        for (int k = 0; k < 32; k++) {
            float a0 = As[ty * 4 + 0][k];
            float a1 = As[ty * 4 + 1][k];
            float a2 = As[ty * 4 + 2][k];
            float a3 = As[ty * 4 + 3][k];
            float4 b = *(const float4*)&Bs[k][tx * 4];
            acc[0][0] += a0 * b.x; acc[0][1] += a0 * b.y; acc[0][2] += a0 * b.z; acc[0][3] += a0 * b.w;
            acc[1][0] += a1 * b.x; acc[1][1] += a1 * b.y; acc[1][2] += a1 * b.z; acc[1][3] += a1 * b.w;
            acc[2][0] += a2 * b.x; acc[2][1] += a2 * b.y; acc[2][2] += a2 * b.z; acc[2][3] += a2 * b.w;
            acc[3][0] += a3 * b.x; acc[3][1] += a3 * b.y; acc[3][2] += a3 * b.z; acc[3][3] += a3 * b.w;
        }
        __syncthreads();
    }

    float4 bv = *(const float4*)&bias[colBase + tx * 4];
#pragma unroll
    for (int i = 0; i < 4; i++) {
        int gr = rowBase + ty * 4 + i;
        if (gr < M) {
            float4 o;
            o.x = fmaxf(acc[i][0] + bv.x, 0.f);
            o.y = fmaxf(acc[i][1] + bv.y, 0.f);
            o.z = fmaxf(acc[i][2] + bv.z, 0.f);
            o.w = fmaxf(acc[i][3] + bv.w, 0.f);
            *(float4*)&C[(long)gr * ldc + colBase + tx * 4] = o;
        }
    }
}

// ---------------- pooling ----------------
__global__ void gstart_kernel(const int* __restrict__ batch) {
    int g = blockIdx.x * blockDim.x + threadIdx.x;
    if (g > GG) return;
    int lo = 0, hi = NN;
    while (lo < hi) {
        int mid = (lo + hi) >> 1;
        if (batch[mid] < g) lo = mid + 1; else hi = mid;
    }
    g_gstart[g] = lo;
}

__global__ __launch_bounds__(256) void pool_kernel(
    const float* __restrict__ node_embed, float* __restrict__ graph_out)
{
    int g = blockIdx.x;
    int beg = g_gstart[g];
    int end = g_gstart[g + 1];
    int cnt = end - beg; if (cnt < 1) cnt = 1;
    float inv = 1.0f / (float)cnt;
    for (int d = threadIdx.x; d < LL * DD; d += blockDim.x) {
        float s = 0.f;
        for (int n = beg; n < end; n++) s += node_embed[(long)n * (LL * DD) + d];
        graph_out[(long)g * (LL * DD) + d] = s * inv;
    }
}

// ---------------- launch ----------------
extern "C" void kernel_launch(void* const* d_in, const int* in_sizes, int n_in,
                              void* d_out, int out_size)
{
    const float* x     = (const float*)d_in[0];
    const int*   ei    = (const int*)d_in[1];
    const int*   batch = (const int*)d_in[2];
    const float* Ws1   = (const float*)d_in[3];
    const float* bs1   = (const float*)d_in[4];
    const float* Ws2   = (const float*)d_in[5];
    const float* bs2   = (const float*)d_in[6];

    float* out       = (float*)d_out;
    float* graph_out = out;                      // [G, L*D]
    float* node_out  = out + (long)GG * LL * DD; // [N, L*D]

    float* agg_ptr; float* t_ptr;
    cudaGetSymbolAddress((void**)&agg_ptr, g_agg);
    cudaGetSymbolAddress((void**)&t_ptr, g_t);

    // CSR build (once per launch, reused by 3 layers)
    zero_deg_kernel<<<(NN + 255) / 256, 256>>>();
    count_kernel<<<(EE + 255) / 256, 256>>>(ei);
    scan_kernel<<<1, 1024>>>();
    copy_cursor_kernel<<<(NN + 255) / 256, 256>>>();
    fill_kernel<<<(EE + 255) / 256, 256>>>(ei);

    dim3 gemm_grid((NN + 63) / 64, 4);

    const float* h = x;
    int hstride = DD;
    for (int i = 0; i < LL; i++) {
        // agg = h + scatter_sum(h[src] -> dst)
        aggregate_kernel<<<(NN * 32 + 255) / 256, 256>>>(h, hstride);
        // t = relu(agg @ Ws1[i] + bs1[i])
        gemm_bias_relu<<<gemm_grid, 256>>>(agg_ptr, DD,
                                           Ws1 + (long)i * DD * DD,
                                           bs1 + (long)i * DD,
                                           t_ptr, DD, NN);
        // h = relu(t @ Ws2[i] + bs2[i])  -> directly into node_embed slice
        gemm_bias_relu<<<gemm_grid, 256>>>(t_ptr, DD,
                                           Ws2 + (long)i * DD * DD,
                                           bs2 + (long)i * DD,
                                           node_out + (long)i * DD, LL * DD, NN);
        h = node_out + (long)i * DD;
        hstride = LL * DD;
    }

    // pooling
    gstart_kernel<<<(GG + 1 + 255) / 256, 256>>>(batch);
    pool_kernel<<<GG, 256>>>(node_out, graph_out);
}

// round 12
// speedup vs baseline: 1.5569x; 1.5569x over previous
#include <cuda_runtime.h>
#include <cuda_bf16.h>
#include <cstdint>

#define NN 50000
#define EE 800000
#define DD 256
#define LL 3
#define GG 512

// tcgen05 is only legal on arch-specific targets (sm_103a / sm_100a).
// The harness build includes a plain compute_103 PTX pass, which must compile
// a fallback instead.
#if defined(__CUDA_ARCH_FEAT_SM103_ALL) || defined(__CUDA_ARCH_FEAT_SM100_ALL) || \
    defined(__CUDA_ARCH_FEAT_SM101_ALL) || defined(__CUDA_ARCH_SPECIFIC__)
#define HAS_TCGEN05 1
#else
#define HAS_TCGEN05 0
#endif

// ==================== PTX helpers (sm_103a-only) ====================
#if HAS_TCGEN05
__device__ __forceinline__ uint32_t smem_to_u32(const void* p) {
    uint32_t a;
    asm("{ .reg .u64 t; cvta.to.shared.u64 t, %1; cvt.u32.u64 %0, t; }" : "=r"(a) : "l"(p));
    return a;
}
__device__ __forceinline__ uint32_t elect_one_pred() {
    uint32_t pred;
    asm volatile("{\n\t.reg .pred p;\n\telect.sync _|p, 0xFFFFFFFF;\n\tselp.b32 %0, 1, 0, p;\n\t}" : "=r"(pred));
    return pred;
}
#define MBARRIER_INIT(addr, cnt) \
    asm volatile("mbarrier.init.shared.b64 [%0], %1;" :: "r"((uint32_t)(addr)), "r"((uint32_t)(cnt)) : "memory")
#define MBARRIER_WAIT_PARITY(mbar_smem_addr, phase_parity) do { \
    uint32_t _mbar = (uint32_t)(mbar_smem_addr); \
    uint32_t _parity = (uint32_t)(phase_parity); \
    uint32_t _done; \
    asm volatile("{\n\t.reg .pred p;\n\t" \
        "mbarrier.try_wait.parity.acquire.cta.shared::cta.b64 p, [%1], %2;\n\t" \
        "selp.b32 %0, 1, 0, p;\n\t}" \
        : "=r"(_done) : "r"(_mbar), "r"(_parity) : "memory"); \
    if (!_done) { \
        asm volatile("{\n\t.reg .pred P1;\n\t" \
            "WAIT_LOOP_%=:\n\t" \
            "mbarrier.try_wait.parity.acquire.cta.shared::cta.b64 P1, [%0], %1, 0x989680;\n\t" \
            "@P1 bra.uni WAIT_DONE_%=;\n\t" \
            "bra.uni WAIT_LOOP_%=;\n\t" \
            "WAIT_DONE_%=:\n\t}" \
            :: "r"(_mbar), "r"(_parity) : "memory"); \
    } \
} while(0)
#define TCGEN05_ALLOC(smem_result_addr, nCols) \
    asm volatile("tcgen05.alloc.cta_group::1.sync.aligned.shared::cta.b32 [%0], %1;" \
        :: "r"((uint32_t)(smem_result_addr)), "r"((uint32_t)(nCols)) : "memory")
#define TCGEN05_DEALLOC(tmem_addr, nCols) \
    asm volatile("tcgen05.dealloc.cta_group::1.sync.aligned.b32 %0, %1;" :: "r"(tmem_addr), "r"((uint32_t)(nCols)))
#define TCGEN05_RELINQUISH() \
    asm volatile("tcgen05.relinquish_alloc_permit.cta_group::1.sync.aligned;")
#define TCGEN05_COMMIT(mbar_smem_addr) \
    asm volatile("tcgen05.commit.cta_group::1.mbarrier::arrive::one.shared::cluster.b64 [%0];" \
        :: "r"((uint32_t)(mbar_smem_addr)) : "memory")
#define TCGEN05_WAIT_LD() asm volatile("tcgen05.wait::ld.sync.aligned;" ::: "memory")
#define TCGEN05_FENCE_AFTER() asm volatile("tcgen05.fence::after_thread_sync;" ::: "memory")
#define FENCE_PROXY_ASYNC_SHARED_CTA() asm volatile("fence.proxy.async.shared::cta;" ::: "memory")
#define TCGEN05_LD_32X32B_X32(r, tmem_addr) \
    asm volatile("tcgen05.ld.sync.aligned.32x32b.x32.b32 " \
        "{%0, %1, %2, %3, %4, %5, %6, %7, %8, %9, %10, %11, %12, %13, %14, %15, " \
        " %16, %17, %18, %19, %20, %21, %22, %23, %24, %25, %26, %27, %28, %29, %30, %31}, [%32];" \
        : "=r"((r)[0]),  "=r"((r)[1]),  "=r"((r)[2]),  "=r"((r)[3]), \
          "=r"((r)[4]),  "=r"((r)[5]),  "=r"((r)[6]),  "=r"((r)[7]), \
          "=r"((r)[8]),  "=r"((r)[9]),  "=r"((r)[10]), "=r"((r)[11]), \
          "=r"((r)[12]), "=r"((r)[13]), "=r"((r)[14]), "=r"((r)[15]), \
          "=r"((r)[16]), "=r"((r)[17]), "=r"((r)[18]), "=r"((r)[19]), \
          "=r"((r)[20]), "=r"((r)[21]), "=r"((r)[22]), "=r"((r)[23]), \
          "=r"((r)[24]), "=r"((r)[25]), "=r"((r)[26]), "=r"((r)[27]), \
          "=r"((r)[28]), "=r"((r)[29]), "=r"((r)[30]), "=r"((r)[31]) \
        : "r"(tmem_addr))

static constexpr uint64_t SMEM_DESC_BASE_SW128 =
    (uint64_t(2) << 61) | (uint64_t(1) << 46) | (uint64_t(64) << 32) | (uint64_t(1) << 16);
#define MAKE_SMEM_DESC(base_addr) (SMEM_DESC_BASE_SW128 | ((uint64_t)((base_addr) >> 4) & 0x3FFF))

// SS-mode bf16 MMA, cta_group::1, fp32 accumulate
__device__ __forceinline__ void mma_f16_ss(uint32_t d, uint64_t a, uint64_t b, uint32_t idesc, int en) {
    asm volatile("{\n\t.reg .pred p;\n\tsetp.ne.u32 p, %4, 0;\n\t"
        "tcgen05.mma.cta_group::1.kind::f16 [%0], %1, %2, %3, {%5, %5, %5, %5}, p;\n\t}"
        :: "r"(d), "l"(a), "l"(b), "r"(idesc), "r"((uint32_t)en), "r"(0u) : "memory");
}

// idesc: dtype F32 (1<<4), atype BF16 (1<<7), btype BF16 (1<<10), N=256 (32<<17), M=128 (8<<24)
static constexpr uint32_t GEMM_IDESC =
    (1u << 4) | (1u << 7) | (1u << 10) | ((256u / 8) << 17) | ((128u / 16) << 24);
#endif // HAS_TCGEN05

#define SMEM_SWIZZLE_128B(byte_offset) ((byte_offset) ^ (((byte_offset) >> 3) & 0x70))

// ==================== scratch (16B+ aligned for vector access) ====================
__device__ __align__(256) __nv_bfloat16 g_agg_hi[NN * DD];
__device__ __align__(256) __nv_bfloat16 g_agg_lo[NN * DD];
__device__ __align__(256) __nv_bfloat16 g_t_hi[NN * DD];
__device__ __align__(256) __nv_bfloat16 g_t_lo[NN * DD];
__device__ __align__(256) __nv_bfloat16 g_w1_hi[LL * DD * DD];   // transposed [l][n][k]
__device__ __align__(256) __nv_bfloat16 g_w1_lo[LL * DD * DD];
__device__ __align__(256) __nv_bfloat16 g_w2_hi[LL * DD * DD];
__device__ __align__(256) __nv_bfloat16 g_w2_lo[LL * DD * DD];
__device__ int g_deg[NN];
__device__ int g_cursor[NN];
__device__ int g_rowstart[NN + 1];
__device__ int g_esrc[EE];
__device__ int g_gstart[GG + 1];

// ==================== CSR build ====================
__global__ void zero_deg_kernel() {
    int i = blockIdx.x * blockDim.x + threadIdx.x;
    if (i < NN) g_deg[i] = 0;
}
__global__ void count_kernel(const int* __restrict__ ei) {
    int e = blockIdx.x * blockDim.x + threadIdx.x;
    if (e < EE) atomicAdd(&g_deg[ei[EE + e]], 1);
}
__global__ void scan_kernel() {
    __shared__ int partials[1024];
    const int n = NN;
    int tid = threadIdx.x;
    int chunk = (n + 1023) / 1024;
    int beg = tid * chunk;
    int end = beg + chunk; if (end > n) end = n;
    int sum = 0;
    for (int i = beg; i < end; i++) sum += g_deg[i];
    partials[tid] = sum;
    __syncthreads();
    for (int off = 1; off < 1024; off <<= 1) {
        int v = 0;
        if (tid >= off) v = partials[tid - off];
        __syncthreads();
        partials[tid] += v;
        __syncthreads();
    }
    int run = (tid == 0) ? 0 : partials[tid - 1];
    for (int i = beg; i < end; i++) { g_rowstart[i] = run; run += g_deg[i]; }
    if (tid == 0) g_rowstart[n] = EE;
}
__global__ void copy_cursor_kernel() {
    int i = blockIdx.x * blockDim.x + threadIdx.x;
    if (i < NN) g_cursor[i] = g_rowstart[i];
}
__global__ void fill_kernel(const int* __restrict__ ei) {
    int e = blockIdx.x * blockDim.x + threadIdx.x;
    if (e < EE) {
        int dst = ei[EE + e];
        int pos = atomicAdd(&g_cursor[dst], 1);
        g_esrc[pos] = ei[e];
    }
}

// ==================== weight prep: transpose + bf16 split ====================
__global__ void prep_weights(const float* __restrict__ Ws1, const float* __restrict__ Ws2) {
    int i = blockIdx.x * blockDim.x + threadIdx.x;
    if (i >= LL * DD * DD) return;
    int l = i >> 16;
    int r = i & 65535;
    int n = r >> 8;
    int k = r & 255;
    float w1 = Ws1[l * 65536 + k * 256 + n];
    __nv_bfloat16 h1 = __float2bfloat16(w1);
    g_w1_hi[i] = h1;
    g_w1_lo[i] = __float2bfloat16(w1 - __bfloat162float(h1));
    float w2 = Ws2[l * 65536 + k * 256 + n];
    __nv_bfloat16 h2 = __float2bfloat16(w2);
    g_w2_hi[i] = h2;
    g_w2_lo[i] = __float2bfloat16(w2 - __bfloat162float(h2));
}

// ==================== aggregation -> bf16 hi/lo ====================
__device__ __forceinline__ uint32_t pack_hi2(float a, float b, uint32_t& lo_out) {
    __nv_bfloat16 ha = __float2bfloat16(a);
    __nv_bfloat16 hb = __float2bfloat16(b);
    __nv_bfloat16 la = __float2bfloat16(a - __bfloat162float(ha));
    __nv_bfloat16 lb = __float2bfloat16(b - __bfloat162float(hb));
    lo_out = (uint32_t)__bfloat16_as_ushort(la) | ((uint32_t)__bfloat16_as_ushort(lb) << 16);
    return (uint32_t)__bfloat16_as_ushort(ha) | ((uint32_t)__bfloat16_as_ushort(hb) << 16);
}

__global__ __launch_bounds__(256) void aggregate_kernel(const float* __restrict__ h, int hstride) {
    int node = (blockIdx.x * blockDim.x + threadIdx.x) >> 5;
    if (node >= NN) return;
    int lane = threadIdx.x & 31;
    int beg = g_rowstart[node];
    int end = g_rowstart[node + 1];
    int d0 = lane * 4;
    int d1 = 128 + lane * 4;
    float4 acc0 = make_float4(0.f, 0.f, 0.f, 0.f);
    float4 acc1 = make_float4(0.f, 0.f, 0.f, 0.f);
    for (int e = beg; e < end; e++) {
        int s = __ldg(&g_esrc[e]);
        const float* hs = h + (long)s * hstride;
        float4 a = *(const float4*)(hs + d0);
        float4 b = *(const float4*)(hs + d1);
        acc0.x += a.x; acc0.y += a.y; acc0.z += a.z; acc0.w += a.w;
        acc1.x += b.x; acc1.y += b.y; acc1.z += b.z; acc1.w += b.w;
    }
    const float* hn = h + (long)node * hstride;
    float4 a = *(const float4*)(hn + d0);
    float4 b = *(const float4*)(hn + d1);
    acc0.x += a.x; acc0.y += a.y; acc0.z += a.z; acc0.w += a.w;
    acc1.x += b.x; acc1.y += b.y; acc1.z += b.z; acc1.w += b.w;

    uint32_t l01, l23, m01, m23;
    uint32_t h01 = pack_hi2(acc0.x, acc0.y, l01);
    uint32_t h23 = pack_hi2(acc0.z, acc0.w, l23);
    uint32_t i01 = pack_hi2(acc1.x, acc1.y, m01);
    uint32_t i23 = pack_hi2(acc1.z, acc1.w, m23);
    __nv_bfloat16* oh = g_agg_hi + (long)node * DD;
    __nv_bfloat16* ol = g_agg_lo + (long)node * DD;
    *(uint2*)(oh + d0) = make_uint2(h01, h23);
    *(uint2*)(ol + d0) = make_uint2(l01, l23);
    *(uint2*)(oh + d1) = make_uint2(i01, i23);
    *(uint2*)(ol + d1) = make_uint2(m01, m23);
}

// ==================== GEMM: C = relu(A @ Wt^T + b) ====================
// A (split hi/lo bf16) [M,256]; Wt (split) [256 n,256 k] row-major (pre-transposed)
// mode 0: write bf16 hi/lo into outH/outL (stride 256)
// mode 1: write fp32 into outF (stride ldc)
// sm_103a path: tcgen05, tile M=128/N=256, K chunked by 64, 3 split products.
// non-a PTX pass: plain FFMA fallback (never executed; cubin preferred at runtime).
#define REL_TM   0
#define REL_MBAR 8
#define REL_AH   1024
#define REL_AL   (1024 + 16384)
#define REL_BH   (1024 + 32768)
#define REL_BL   (1024 + 65536)
#define SMEM_END (1024 + 98304)
#define GEMM_SMEM_BYTES (SMEM_END + 1024)

__global__ __launch_bounds__(256, 2) __cluster_dims__(1, 1, 1)
void gemm_tc(const __nv_bfloat16* __restrict__ Ahi, const __nv_bfloat16* __restrict__ Alo,
             const __nv_bfloat16* __restrict__ Bhi, const __nv_bfloat16* __restrict__ Blo,
             const float* __restrict__ bias,
             float* __restrict__ outF, int ldc,
             __nv_bfloat16* __restrict__ outH, __nv_bfloat16* __restrict__ outL,
             int M, int mode)
{
#if HAS_TCGEN05
    extern __shared__ char smem_raw[];
    uint32_t sraw = smem_to_u32(smem_raw);
    uint32_t sb = (sraw + 1023u) & ~1023u;       // 1024-align for SW128
    char* smem = smem_raw + (sb - sraw);

    int tid = threadIdx.x;
    int rowBase = blockIdx.x * 128;

    if (tid < 32) {
        TCGEN05_ALLOC(sb + REL_TM, 256);
        TCGEN05_RELINQUISH();
    }
    if (tid == 0) MBARRIER_INIT(sb + REL_MBAR, 1);
    __syncthreads();
    uint32_t tm;
    asm volatile("ld.shared.b32 %0, [%1];" : "=r"(tm) : "r"(sb + REL_TM));

    uint64_t dAH = MAKE_SMEM_DESC(sb + REL_AH);
    uint64_t dAL = MAKE_SMEM_DESC(sb + REL_AL);
    uint64_t dBH = MAKE_SMEM_DESC(sb + REL_BH);
    uint64_t dBL = MAKE_SMEM_DESC(sb + REL_BL);

    for (int c = 0; c < 4; c++) {
        int k0 = c * 64;
        // A chunk [128 x 64] bf16: 128B rows, SW128
        for (int i = tid; i < 128 * 8; i += 256) {
            int r = i >> 3, q = i & 7;
            uint32_t sw = SMEM_SWIZZLE_128B((uint32_t)(r * 128 + q * 16));
            uint4 vh = make_uint4(0, 0, 0, 0), vl = make_uint4(0, 0, 0, 0);
            int gr = rowBase + r;
            if (gr < M) {
                vh = *(const uint4*)(Ahi + (size_t)gr * 256 + k0 + q * 8);
                vl = *(const uint4*)(Alo + (size_t)gr * 256 + k0 + q * 8);
            }
            *(uint4*)(smem + REL_AH + sw) = vh;
            *(uint4*)(smem + REL_AL + sw) = vl;
        }
        // B chunk [256 x 64] bf16
        for (int i = tid; i < 256 * 8; i += 256) {
            int n = i >> 3, q = i & 7;
            uint32_t sw = SMEM_SWIZZLE_128B((uint32_t)(n * 128 + q * 16));
            *(uint4*)(smem + REL_BH + sw) = *(const uint4*)(Bhi + (size_t)n * 256 + k0 + q * 8);
            *(uint4*)(smem + REL_BL + sw) = *(const uint4*)(Blo + (size_t)n * 256 + k0 + q * 8);
        }
        FENCE_PROXY_ASYNC_SHARED_CTA();
        __syncthreads();

        if (tid < 32 && elect_one_pred()) {
            #pragma unroll
            for (int s = 0; s < 4; s++) {
                uint64_t off = (uint64_t)(2 * s);
                mma_f16_ss(tm, dAH + off, dBH + off, GEMM_IDESC, !(c == 0 && s == 0));
                mma_f16_ss(tm, dAL + off, dBH + off, GEMM_IDESC, 1);
                mma_f16_ss(tm, dAH + off, dBL + off, GEMM_IDESC, 1);
            }
            TCGEN05_COMMIT(sb + REL_MBAR);
        }
        MBARRIER_WAIT_PARITY(sb + REL_MBAR, c & 1);
        __syncthreads();
    }

    // epilogue
    TCGEN05_FENCE_AFTER();
    int wg = tid >> 7;          // warpgroup: 0 -> cols 0-127, 1 -> cols 128-255
    int wr = tid & 127;         // M row within tile (= TMEM lane)
    int m = rowBase + wr;
    int colWG = wg << 7;
    for (int c = 0; c < 4; c++) {
        uint32_t d[32];
        TCGEN05_LD_32X32B_X32(d, tm + colWG + c * 32);
        TCGEN05_WAIT_LD();
        int col0 = colWG + c * 32;
        if (m < M) {
            if (mode == 0) {
                uint32_t ph[16], pl[16];
                #pragma unroll
                for (int j = 0; j < 16; j++) {
                    float v0 = fmaxf(__uint_as_float(d[2 * j]) + __ldg(&bias[col0 + 2 * j]), 0.f);
                    float v1 = fmaxf(__uint_as_float(d[2 * j + 1]) + __ldg(&bias[col0 + 2 * j + 1]), 0.f);
                    ph[j] = pack_hi2(v0, v1, pl[j]);
                }
                uint32_t* oh = (uint32_t*)(outH + (size_t)m * 256 + col0);
                uint32_t* ol = (uint32_t*)(outL + (size_t)m * 256 + col0);
                #pragma unroll
                for (int j = 0; j < 16; j++) { oh[j] = ph[j]; ol[j] = pl[j]; }
            } else {
                float* o = outF + (size_t)m * ldc + col0;
                #pragma unroll
                for (int j = 0; j < 8; j++) {
                    float4 v;
                    v.x = fmaxf(__uint_as_float(d[4 * j + 0]) + __ldg(&bias[col0 + 4 * j + 0]), 0.f);
                    v.y = fmaxf(__uint_as_float(d[4 * j + 1]) + __ldg(&bias[col0 + 4 * j + 1]), 0.f);
                    v.z = fmaxf(__uint_as_float(d[4 * j + 2]) + __ldg(&bias[col0 + 4 * j + 2]), 0.f);
                    v.w = fmaxf(__uint_as_float(d[4 * j + 3]) + __ldg(&bias[col0 + 4 * j + 3]), 0.f);
                    *(float4*)(o + 4 * j) = v;
                }
            }
        }
    }
    __syncthreads();
    if (tid < 32) TCGEN05_DEALLOC(tm, 256);
#else
    // Fallback for the non-'a' PTX pass. Correct but slow; at runtime the
    // exact-match sm_103a cubin is preferred, so this should never execute.
    int tid = threadIdx.x;
    int rowBase = blockIdx.x * 128;
    int m = rowBase + (tid >> 1);
    int nBase = (tid & 1) * 128;
    if (m < M) {
        for (int n = nBase; n < nBase + 128; n++) {
            float acc = 0.f;
            for (int k = 0; k < 256; k++) {
                float av = __bfloat162float(Ahi[(size_t)m * 256 + k]) +
                           __bfloat162float(Alo[(size_t)m * 256 + k]);
                float bv = __bfloat162float(Bhi[(size_t)n * 256 + k]) +
                           __bfloat162float(Blo[(size_t)n * 256 + k]);
                acc += av * bv;
            }
            acc = fmaxf(acc + bias[n], 0.f);
            if (mode == 0) {
                __nv_bfloat16 hh = __float2bfloat16(acc);
                outH[(size_t)m * 256 + n] = hh;
                outL[(size_t)m * 256 + n] = __float2bfloat16(acc - __bfloat162float(hh));
            } else {
                outF[(size_t)m * ldc + n] = acc;
            }
        }
    }
#endif
}

// ==================== pooling ====================
__global__ void gstart_kernel(const int* __restrict__ batch) {
    int g = blockIdx.x * blockDim.x + threadIdx.x;
    if (g > GG) return;
    int lo = 0, hi = NN;
    while (lo < hi) {
        int mid = (lo + hi) >> 1;
        if (batch[mid] < g) lo = mid + 1; else hi = mid;
    }
    g_gstart[g] = lo;
}
__global__ __launch_bounds__(256) void pool_kernel(
    const float* __restrict__ node_embed, float* __restrict__ graph_out)
{
    int g = blockIdx.x;
    int beg = g_gstart[g];
    int end = g_gstart[g + 1];
    int cnt = end - beg; if (cnt < 1) cnt = 1;
    float inv = 1.0f / (float)cnt;
    for (int d = threadIdx.x; d < LL * DD; d += blockDim.x) {
        float s = 0.f;
        for (int n = beg; n < end; n++) s += node_embed[(long)n * (LL * DD) + d];
        graph_out[(long)g * (LL * DD) + d] = s * inv;
    }
}

// ==================== launch ====================
extern "C" void kernel_launch(void* const* d_in, const int* in_sizes, int n_in,
                              void* d_out, int out_size)
{
    const float* x     = (const float*)d_in[0];
    const int*   ei    = (const int*)d_in[1];
    const int*   batch = (const int*)d_in[2];
    const float* Ws1   = (const float*)d_in[3];
    const float* bs1   = (const float*)d_in[4];
    const float* Ws2   = (const float*)d_in[5];
    const float* bs2   = (const float*)d_in[6];

    float* out       = (float*)d_out;
    float* graph_out = out;
    float* node_out  = out + (long)GG * LL * DD;

    __nv_bfloat16 *aggH, *aggL, *tH, *tL, *w1H, *w1L, *w2H, *w2L;
    cudaGetSymbolAddress((void**)&aggH, g_agg_hi);
    cudaGetSymbolAddress((void**)&aggL, g_agg_lo);
    cudaGetSymbolAddress((void**)&tH, g_t_hi);
    cudaGetSymbolAddress((void**)&tL, g_t_lo);
    cudaGetSymbolAddress((void**)&w1H, g_w1_hi);
    cudaGetSymbolAddress((void**)&w1L, g_w1_lo);
    cudaGetSymbolAddress((void**)&w2H, g_w2_hi);
    cudaGetSymbolAddress((void**)&w2L, g_w2_lo);

    cudaFuncSetAttribute(gemm_tc, cudaFuncAttributeMaxDynamicSharedMemorySize, GEMM_SMEM_BYTES);

    // CSR build + weight prep
    zero_deg_kernel<<<(NN + 255) / 256, 256>>>();
    count_kernel<<<(EE + 255) / 256, 256>>>(ei);
    scan_kernel<<<1, 1024>>>();
    copy_cursor_kernel<<<(NN + 255) / 256, 256>>>();
    fill_kernel<<<(EE + 255) / 256, 256>>>(ei);
    prep_weights<<<(LL * DD * DD + 255) / 256, 256>>>(Ws1, Ws2);

    int gemm_grid = (NN + 127) / 128;   // 391

    const float* h = x;
    int hstride = DD;
    for (int i = 0; i < LL; i++) {
        aggregate_kernel<<<(NN * 32 + 255) / 256, 256>>>(h, hstride);
        // t = relu(agg @ W1 + b1) -> bf16 hi/lo
        gemm_tc<<<gemm_grid, 256, GEMM_SMEM_BYTES>>>(
            aggH, aggL, w1H + (long)i * DD * DD, w1L + (long)i * DD * DD,
            bs1 + (long)i * DD, nullptr, 0, tH, tL, NN, 0);
        // h = relu(t @ W2 + b2) -> fp32 node_embed slice
        gemm_tc<<<gemm_grid, 256, GEMM_SMEM_BYTES>>>(
            tH, tL, w2H + (long)i * DD * DD, w2L + (long)i * DD * DD,
            bs2 + (long)i * DD, node_out + (long)i * DD, LL * DD, nullptr, nullptr, NN, 1);
        h = node_out + (long)i * DD;
        hstride = LL * DD;
    }

    gstart_kernel<<<(GG + 1 + 255) / 256, 256>>>(batch);
    pool_kernel<<<GG, 256>>>(node_out, graph_out);
}

// round 14
// speedup vs baseline: 1.5899x; 1.0212x over previous
#include <cuda_runtime.h>
#include <cuda_bf16.h>
#include <cstdint>

#define NN 50000
#define EE 800000
#define DD 256
#define LL 3
#define GG 512

// tcgen05 is only legal on arch-specific targets (sm_103a / sm_100a).
// The harness build includes a plain compute_103 PTX pass, which must compile
// a fallback instead.
#if defined(__CUDA_ARCH_FEAT_SM103_ALL) || defined(__CUDA_ARCH_FEAT_SM100_ALL) || \
    defined(__CUDA_ARCH_FEAT_SM101_ALL) || defined(__CUDA_ARCH_SPECIFIC__)
#define HAS_TCGEN05 1
#else
#define HAS_TCGEN05 0
#endif

// ==================== PTX helpers (sm_103a-only) ====================
#if HAS_TCGEN05
__device__ __forceinline__ uint32_t smem_to_u32(const void* p) {
    uint32_t a;
    asm("{ .reg .u64 t; cvta.to.shared.u64 t, %1; cvt.u32.u64 %0, t; }" : "=r"(a) : "l"(p));
    return a;
}
__device__ __forceinline__ uint32_t elect_one_pred() {
    uint32_t pred;
    asm volatile("{\n\t.reg .pred p;\n\telect.sync _|p, 0xFFFFFFFF;\n\tselp.b32 %0, 1, 0, p;\n\t}" : "=r"(pred));
    return pred;
}
#define MBARRIER_INIT(addr, cnt) \
    asm volatile("mbarrier.init.shared.b64 [%0], %1;" :: "r"((uint32_t)(addr)), "r"((uint32_t)(cnt)) : "memory")
#define MBARRIER_WAIT_PARITY(mbar_smem_addr, phase_parity) do { \
    uint32_t _mbar = (uint32_t)(mbar_smem_addr); \
    uint32_t _parity = (uint32_t)(phase_parity); \
    uint32_t _done; \
    asm volatile("{\n\t.reg .pred p;\n\t" \
        "mbarrier.try_wait.parity.acquire.cta.shared::cta.b64 p, [%1], %2;\n\t" \
        "selp.b32 %0, 1, 0, p;\n\t}" \
        : "=r"(_done) : "r"(_mbar), "r"(_parity) : "memory"); \
    if (!_done) { \
        asm volatile("{\n\t.reg .pred P1;\n\t" \
            "WAIT_LOOP_%=:\n\t" \
            "mbarrier.try_wait.parity.acquire.cta.shared::cta.b64 P1, [%0], %1, 0x989680;\n\t" \
            "@P1 bra.uni WAIT_DONE_%=;\n\t" \
            "bra.uni WAIT_LOOP_%=;\n\t" \
            "WAIT_DONE_%=:\n\t}" \
            :: "r"(_mbar), "r"(_parity) : "memory"); \
    } \
} while(0)
#define TCGEN05_ALLOC(smem_result_addr, nCols) \
    asm volatile("tcgen05.alloc.cta_group::1.sync.aligned.shared::cta.b32 [%0], %1;" \
        :: "r"((uint32_t)(smem_result_addr)), "r"((uint32_t)(nCols)) : "memory")
#define TCGEN05_DEALLOC(tmem_addr, nCols) \
    asm volatile("tcgen05.dealloc.cta_group::1.sync.aligned.b32 %0, %1;" :: "r"(tmem_addr), "r"((uint32_t)(nCols)))
#define TCGEN05_RELINQUISH() \
    asm volatile("tcgen05.relinquish_alloc_permit.cta_group::1.sync.aligned;")
#define TCGEN05_COMMIT(mbar_smem_addr) \
    asm volatile("tcgen05.commit.cta_group::1.mbarrier::arrive::one.shared::cluster.b64 [%0];" \
        :: "r"((uint32_t)(mbar_smem_addr)) : "memory")
#define TCGEN05_WAIT_LD() asm volatile("tcgen05.wait::ld.sync.aligned;" ::: "memory")
#define TCGEN05_FENCE_AFTER() asm volatile("tcgen05.fence::after_thread_sync;" ::: "memory")
#define FENCE_PROXY_ASYNC_SHARED_CTA() asm volatile("fence.proxy.async.shared::cta;" ::: "memory")
#define TCGEN05_LD_32X32B_X32(r, tmem_addr) \
    asm volatile("tcgen05.ld.sync.aligned.32x32b.x32.b32 " \
        "{%0, %1, %2, %3, %4, %5, %6, %7, %8, %9, %10, %11, %12, %13, %14, %15, " \
        " %16, %17, %18, %19, %20, %21, %22, %23, %24, %25, %26, %27, %28, %29, %30, %31}, [%32];" \
        : "=r"((r)[0]),  "=r"((r)[1]),  "=r"((r)[2]),  "=r"((r)[3]), \
          "=r"((r)[4]),  "=r"((r)[5]),  "=r"((r)[6]),  "=r"((r)[7]), \
          "=r"((r)[8]),  "=r"((r)[9]),  "=r"((r)[10]), "=r"((r)[11]), \
          "=r"((r)[12]), "=r"((r)[13]), "=r"((r)[14]), "=r"((r)[15]), \
          "=r"((r)[16]), "=r"((r)[17]), "=r"((r)[18]), "=r"((r)[19]), \
          "=r"((r)[20]), "=r"((r)[21]), "=r"((r)[22]), "=r"((r)[23]), \
          "=r"((r)[24]), "=r"((r)[25]), "=r"((r)[26]), "=r"((r)[27]), \
          "=r"((r)[28]), "=r"((r)[29]), "=r"((r)[30]), "=r"((r)[31]) \
        : "r"(tmem_addr))

static constexpr uint64_t SMEM_DESC_BASE_SW128 =
    (uint64_t(2) << 61) | (uint64_t(1) << 46) | (uint64_t(64) << 32) | (uint64_t(1) << 16);
#define MAKE_SMEM_DESC(base_addr) (SMEM_DESC_BASE_SW128 | ((uint64_t)((base_addr) >> 4) & 0x3FFF))

// SS-mode bf16 MMA, cta_group::1, fp32 accumulate
__device__ __forceinline__ void mma_f16_ss(uint32_t d, uint64_t a, uint64_t b, uint32_t idesc, int en) {
    asm volatile("{\n\t.reg .pred p;\n\tsetp.ne.u32 p, %4, 0;\n\t"
        "tcgen05.mma.cta_group::1.kind::f16 [%0], %1, %2, %3, {%5, %5, %5, %5}, p;\n\t}"
        :: "r"(d), "l"(a), "l"(b), "r"(idesc), "r"((uint32_t)en), "r"(0u) : "memory");
}

// idesc: dtype F32 (1<<4), atype BF16 (1<<7), btype BF16 (1<<10), N=256 (32<<17), M=128 (8<<24)
static constexpr uint32_t GEMM_IDESC =
    (1u << 4) | (1u << 7) | (1u << 10) | ((256u / 8) << 17) | ((128u / 16) << 24);
#endif // HAS_TCGEN05

#define SMEM_SWIZZLE_128B(byte_offset) ((byte_offset) ^ (((byte_offset) >> 3) & 0x70))

// ==================== scratch (16B+ aligned for vector access) ====================
__device__ __align__(256) __nv_bfloat16 g_agg_hi[NN * DD];
__device__ __align__(256) __nv_bfloat16 g_agg_lo[NN * DD];
__device__ __align__(256) __nv_bfloat16 g_t_hi[NN * DD];
__device__ __align__(256) __nv_bfloat16 g_t_lo[NN * DD];
__device__ __align__(256) __nv_bfloat16 g_w1_hi[LL * DD * DD];   // transposed [l][n][k]
__device__ __align__(256) __nv_bfloat16 g_w1_lo[LL * DD * DD];
__device__ __align__(256) __nv_bfloat16 g_w2_hi[LL * DD * DD];
__device__ __align__(256) __nv_bfloat16 g_w2_lo[LL * DD * DD];
__device__ int g_deg[NN];
__device__ int g_cursor[NN];
__device__ int g_rowstart[NN + 1];
__device__ int g_esrc[EE];
__device__ int g_gstart[GG + 1];

// ==================== CSR build ====================
__global__ void zero_deg_kernel() {
    int i = blockIdx.x * blockDim.x + threadIdx.x;
    if (i < NN) g_deg[i] = 0;
}
__global__ void count_kernel(const int* __restrict__ ei) {
    int e = blockIdx.x * blockDim.x + threadIdx.x;
    if (e < EE) atomicAdd(&g_deg[ei[EE + e]], 1);
}
__global__ void scan_kernel() {
    __shared__ int partials[1024];
    const int n = NN;
    int tid = threadIdx.x;
    int chunk = (n + 1023) / 1024;
    int beg = tid * chunk;
    int end = beg + chunk; if (end > n) end = n;
    int sum = 0;
    for (int i = beg; i < end; i++) sum += g_deg[i];
    partials[tid] = sum;
    __syncthreads();
    for (int off = 1; off < 1024; off <<= 1) {
        int v = 0;
        if (tid >= off) v = partials[tid - off];
        __syncthreads();
        partials[tid] += v;
        __syncthreads();
    }
    int run = (tid == 0) ? 0 : partials[tid - 1];
    for (int i = beg; i < end; i++) { g_rowstart[i] = run; run += g_deg[i]; }
    if (tid == 0) g_rowstart[n] = EE;
}
__global__ void copy_cursor_kernel() {
    int i = blockIdx.x * blockDim.x + threadIdx.x;
    if (i < NN) g_cursor[i] = g_rowstart[i];
}
__global__ void fill_kernel(const int* __restrict__ ei) {
    int e = blockIdx.x * blockDim.x + threadIdx.x;
    if (e < EE) {
        int dst = ei[EE + e];
        int pos = atomicAdd(&g_cursor[dst], 1);
        g_esrc[pos] = ei[e];
    }
}

// ==================== weight prep: transpose + bf16 split ====================
__global__ void prep_weights(const float* __restrict__ Ws1, const float* __restrict__ Ws2) {
    int i = blockIdx.x * blockDim.x + threadIdx.x;
    if (i >= LL * DD * DD) return;
    int l = i >> 16;
    int r = i & 65535;
    int n = r >> 8;
    int k = r & 255;
    float w1 = Ws1[l * 65536 + k * 256 + n];
    __nv_bfloat16 h1 = __float2bfloat16(w1);
    g_w1_hi[i] = h1;
    g_w1_lo[i] = __float2bfloat16(w1 - __bfloat162float(h1));
    float w2 = Ws2[l * 65536 + k * 256 + n];
    __nv_bfloat16 h2 = __float2bfloat16(w2);
    g_w2_hi[i] = h2;
    g_w2_lo[i] = __float2bfloat16(w2 - __bfloat162float(h2));
}

// ==================== aggregation -> bf16 hi/lo ====================
__device__ __forceinline__ uint32_t pack_hi2(float a, float b, uint32_t& lo_out) {
    __nv_bfloat16 ha = __float2bfloat16(a);
    __nv_bfloat16 hb = __float2bfloat16(b);
    __nv_bfloat16 la = __float2bfloat16(a - __bfloat162float(ha));
    __nv_bfloat16 lb = __float2bfloat16(b - __bfloat162float(hb));
    lo_out = (uint32_t)__bfloat16_as_ushort(la) | ((uint32_t)__bfloat16_as_ushort(lb) << 16);
    return (uint32_t)__bfloat16_as_ushort(ha) | ((uint32_t)__bfloat16_as_ushort(hb) << 16);
}

__global__ __launch_bounds__(256) void aggregate_kernel(const float* __restrict__ h, int hstride) {
    int node = (blockIdx.x * blockDim.x + threadIdx.x) >> 5;
    if (node >= NN) return;
    int lane = threadIdx.x & 31;
    int beg = g_rowstart[node];
    int end = g_rowstart[node + 1];
    int d0 = lane * 4;
    int d1 = 128 + lane * 4;
    float4 acc0 = make_float4(0.f, 0.f, 0.f, 0.f);
    float4 acc1 = make_float4(0.f, 0.f, 0.f, 0.f);
    for (int e = beg; e < end; e++) {
        int s = __ldg(&g_esrc[e]);
        const float* hs = h + (long)s * hstride;
        float4 a = *(const float4*)(hs + d0);
        float4 b = *(const float4*)(hs + d1);
        acc0.x += a.x; acc0.y += a.y; acc0.z += a.z; acc0.w += a.w;
        acc1.x += b.x; acc1.y += b.y; acc1.z += b.z; acc1.w += b.w;
    }
    const float* hn = h + (long)node * hstride;
    float4 a = *(const float4*)(hn + d0);
    float4 b = *(const float4*)(hn + d1);
    acc0.x += a.x; acc0.y += a.y; acc0.z += a.z; acc0.w += a.w;
    acc1.x += b.x; acc1.y += b.y; acc1.z += b.z; acc1.w += b.w;

    uint32_t l01, l23, m01, m23;
    uint32_t h01 = pack_hi2(acc0.x, acc0.y, l01);
    uint32_t h23 = pack_hi2(acc0.z, acc0.w, l23);
    uint32_t i01 = pack_hi2(acc1.x, acc1.y, m01);
    uint32_t i23 = pack_hi2(acc1.z, acc1.w, m23);
    __nv_bfloat16* oh = g_agg_hi + (long)node * DD;
    __nv_bfloat16* ol = g_agg_lo + (long)node * DD;
    *(uint2*)(oh + d0) = make_uint2(h01, h23);
    *(uint2*)(ol + d0) = make_uint2(l01, l23);
    *(uint2*)(oh + d1) = make_uint2(i01, i23);
    *(uint2*)(ol + d1) = make_uint2(m01, m23);
}

// ==================== GEMM: C = relu(A @ Wt^T + b) ====================
// A (split hi/lo bf16) [M,256]; Wt (split) [256 n,256 k] row-major (pre-transposed)
// mode 0: write bf16 hi/lo into outH/outL (stride 256)
// mode 1: write fp32 into outF (stride ldc)
// sm_103a path: tcgen05, tile M=128/N=256, K chunked by 64,
// DOUBLE-BUFFERED k-chunks (2 stages x 96KB), 1 CTA/SM.
// Per-stage mbarriers (2 commits each -> phases 0,1; no parity aliasing):
//   chunk c commits to mbar[c&1]; c>=2 waits mbar[c&1] parity 0 before reuse;
//   epilogue waits mbar1 parity 1 (commit of chunk 3 implies all MMAs done).
// non-a PTX pass: plain FFMA fallback (never executed; cubin preferred at runtime).
#define REL_TM     0
#define REL_MBAR0  8
#define REL_MBAR1  16
#define STG_BASE   1024
#define STG_BYTES  98304          // AH 16K + AL 16K + BH 32K + BL 32K
#define OFF_AH     0
#define OFF_AL     16384
#define OFF_BH     32768
#define OFF_BL     65536
#define GEMM_SMEM_BYTES (STG_BASE + 2 * STG_BYTES + 1024)

__global__ __launch_bounds__(256, 1) __cluster_dims__(1, 1, 1)
void gemm_tc(const __nv_bfloat16* __restrict__ Ahi, const __nv_bfloat16* __restrict__ Alo,
             const __nv_bfloat16* __restrict__ Bhi, const __nv_bfloat16* __restrict__ Blo,
             const float* __restrict__ bias,
             float* __restrict__ outF, int ldc,
             __nv_bfloat16* __restrict__ outH, __nv_bfloat16* __restrict__ outL,
             int M, int mode)
{
#if HAS_TCGEN05
    extern __shared__ char smem_raw[];
    uint32_t sraw = smem_to_u32(smem_raw);
    uint32_t sb = (sraw + 1023u) & ~1023u;       // 1024-align for SW128
    char* smem = smem_raw + (sb - sraw);

    int tid = threadIdx.x;
    int rowBase = blockIdx.x * 128;

    if (tid < 32) {
        TCGEN05_ALLOC(sb + REL_TM, 256);
        TCGEN05_RELINQUISH();
    }
    if (tid == 0) {
        MBARRIER_INIT(sb + REL_MBAR0, 1);
        MBARRIER_INIT(sb + REL_MBAR1, 1);
    }
    __syncthreads();
    uint32_t tm;
    asm volatile("ld.shared.b32 %0, [%1];" : "=r"(tm) : "r"(sb + REL_TM));

    for (int c = 0; c < 4; c++) {
        int st = c & 1;
        uint32_t stage = sb + STG_BASE + (uint32_t)st * STG_BYTES;
        char* sm = smem + STG_BASE + st * STG_BYTES;
        uint32_t mbar = sb + (st ? REL_MBAR1 : REL_MBAR0);
        int k0 = c * 64;

        // Stage reuse hazard: chunk c overwrites the stage used by chunk c-2.
        // Wait for chunk c-2's MMA commit (this stage's first phase).
        if (c >= 2) MBARRIER_WAIT_PARITY(mbar, 0);

        // A chunk [128 x 64] bf16: 128B rows, SW128
        for (int i = tid; i < 128 * 8; i += 256) {
            int r = i >> 3, q = i & 7;
            uint32_t sw = SMEM_SWIZZLE_128B((uint32_t)(r * 128 + q * 16));
            uint4 vh = make_uint4(0, 0, 0, 0), vl = make_uint4(0, 0, 0, 0);
            int gr = rowBase + r;
            if (gr < M) {
                vh = *(const uint4*)(Ahi + (size_t)gr * 256 + k0 + q * 8);
                vl = *(const uint4*)(Alo + (size_t)gr * 256 + k0 + q * 8);
            }
            *(uint4*)(sm + OFF_AH + sw) = vh;
            *(uint4*)(sm + OFF_AL + sw) = vl;
        }
        // B chunk [256 x 64] bf16
        for (int i = tid; i < 256 * 8; i += 256) {
            int n = i >> 3, q = i & 7;
            uint32_t sw = SMEM_SWIZZLE_128B((uint32_t)(n * 128 + q * 16));
            *(uint4*)(sm + OFF_BH + sw) = *(const uint4*)(Bhi + (size_t)n * 256 + k0 + q * 8);
            *(uint4*)(sm + OFF_BL + sw) = *(const uint4*)(Blo + (size_t)n * 256 + k0 + q * 8);
        }
        FENCE_PROXY_ASYNC_SHARED_CTA();
        __syncthreads();

        if (tid < 32 && elect_one_pred()) {
            uint64_t dAH = MAKE_SMEM_DESC(stage + OFF_AH);
            uint64_t dAL = MAKE_SMEM_DESC(stage + OFF_AL);
            uint64_t dBH = MAKE_SMEM_DESC(stage + OFF_BH);
            uint64_t dBL = MAKE_SMEM_DESC(stage + OFF_BL);
            #pragma unroll
            for (int s = 0; s < 4; s++) {
                uint64_t off = (uint64_t)(2 * s);
                mma_f16_ss(tm, dAH + off, dBH + off, GEMM_IDESC, !(c == 0 && s == 0));
                mma_f16_ss(tm, dAL + off, dBH + off, GEMM_IDESC, 1);
                mma_f16_ss(tm, dAH + off, dBL + off, GEMM_IDESC, 1);
            }
            TCGEN05_COMMIT(mbar);
        }
        // no wait here: loads of chunk c+1 overlap MMA of chunk c
    }

    // epilogue: chunk 3 committed to mbar1 (its second phase -> parity 1);
    // commit completion implies ALL previously-issued MMAs are done.
    MBARRIER_WAIT_PARITY(sb + REL_MBAR1, 1);
    TCGEN05_FENCE_AFTER();
    int wg = tid >> 7;          // warpgroup: 0 -> cols 0-127, 1 -> cols 128-255
    int wr = tid & 127;         // M row within tile (= TMEM lane)
    int m = rowBase + wr;
    int colWG = wg << 7;
    for (int c = 0; c < 4; c++) {
        uint32_t d[32];
        TCGEN05_LD_32X32B_X32(d, tm + colWG + c * 32);
        TCGEN05_WAIT_LD();
        int col0 = colWG + c * 32;
        if (m < M) {
            if (mode == 0) {
                uint32_t ph[16], pl[16];
                #pragma unroll
                for (int j = 0; j < 16; j++) {
                    float v0 = fmaxf(__uint_as_float(d[2 * j]) + __ldg(&bias[col0 + 2 * j]), 0.f);
                    float v1 = fmaxf(__uint_as_float(d[2 * j + 1]) + __ldg(&bias[col0 + 2 * j + 1]), 0.f);
                    ph[j] = pack_hi2(v0, v1, pl[j]);
                }
                uint32_t* oh = (uint32_t*)(outH + (size_t)m * 256 + col0);
                uint32_t* ol = (uint32_t*)(outL + (size_t)m * 256 + col0);
                #pragma unroll
                for (int j = 0; j < 16; j++) { oh[j] = ph[j]; ol[j] = pl[j]; }
            } else {
                float* o = outF + (size_t)m * ldc + col0;
                #pragma unroll
                for (int j = 0; j < 8; j++) {
                    float4 v;
                    v.x = fmaxf(__uint_as_float(d[4 * j + 0]) + __ldg(&bias[col0 + 4 * j + 0]), 0.f);
                    v.y = fmaxf(__uint_as_float(d[4 * j + 1]) + __ldg(&bias[col0 + 4 * j + 1]), 0.f);
                    v.z = fmaxf(__uint_as_float(d[4 * j + 2]) + __ldg(&bias[col0 + 4 * j + 2]), 0.f);
                    v.w = fmaxf(__uint_as_float(d[4 * j + 3]) + __ldg(&bias[col0 + 4 * j + 3]), 0.f);
                    *(float4*)(o + 4 * j) = v;
                }
            }
        }
    }
    __syncthreads();
    if (tid < 32) TCGEN05_DEALLOC(tm, 256);
#else
    // Fallback for the non-'a' PTX pass. Correct but slow; at runtime the
    // exact-match sm_103a cubin is preferred, so this should never execute.
    int tid = threadIdx.x;
    int rowBase = blockIdx.x * 128;
    int m = rowBase + (tid >> 1);
    int nBase = (tid & 1) * 128;
    if (m < M) {
        for (int n = nBase; n < nBase + 128; n++) {
            float acc = 0.f;
            for (int k = 0; k < 256; k++) {
                float av = __bfloat162float(Ahi[(size_t)m * 256 + k]) +
                           __bfloat162float(Alo[(size_t)m * 256 + k]);
                float bv = __bfloat162float(Bhi[(size_t)n * 256 + k]) +
                           __bfloat162float(Blo[(size_t)n * 256 + k]);
                acc += av * bv;
            }
            acc = fmaxf(acc + bias[n], 0.f);
            if (mode == 0) {
                __nv_bfloat16 hh = __float2bfloat16(acc);
                outH[(size_t)m * 256 + n] = hh;
                outL[(size_t)m * 256 + n] = __float2bfloat16(acc - __bfloat162float(hh));
            } else {
                outF[(size_t)m * ldc + n] = acc;
            }
        }
    }
#endif
}

// ==================== pooling ====================
__global__ void gstart_kernel(const int* __restrict__ batch) {
    int g = blockIdx.x * blockDim.x + threadIdx.x;
    if (g > GG) return;
    int lo = 0, hi = NN;
    while (lo < hi) {
        int mid = (lo + hi) >> 1;
        if (batch[mid] < g) lo = mid + 1; else hi = mid;
    }
    g_gstart[g] = lo;
}
__global__ __launch_bounds__(256) void pool_kernel(
    const float* __restrict__ node_embed, float* __restrict__ graph_out)
{
    int g = blockIdx.x;
    int beg = g_gstart[g];
    int end = g_gstart[g + 1];
    int cnt = end - beg; if (cnt < 1) cnt = 1;
    float inv = 1.0f / (float)cnt;
    for (int d = threadIdx.x; d < LL * DD; d += blockDim.x) {
        float s = 0.f;
        for (int n = beg; n < end; n++) s += node_embed[(long)n * (LL * DD) + d];
        graph_out[(long)g * (LL * DD) + d] = s * inv;
    }
}

// ==================== launch ====================
extern "C" void kernel_launch(void* const* d_in, const int* in_sizes, int n_in,
                              void* d_out, int out_size)
{
    const float* x     = (const float*)d_in[0];
    const int*   ei    = (const int*)d_in[1];
    const int*   batch = (const int*)d_in[2];
    const float* Ws1   = (const float*)d_in[3];
    const float* bs1   = (const float*)d_in[4];
    const float* Ws2   = (const float*)d_in[5];
    const float* bs2   = (const float*)d_in[6];

    float* out       = (float*)d_out;
    float* graph_out = out;
    float* node_out  = out + (long)GG * LL * DD;

    __nv_bfloat16 *aggH, *aggL, *tH, *tL, *w1H, *w1L, *w2H, *w2L;
    cudaGetSymbolAddress((void**)&aggH, g_agg_hi);
    cudaGetSymbolAddress((void**)&aggL, g_agg_lo);
    cudaGetSymbolAddress((void**)&tH, g_t_hi);
    cudaGetSymbolAddress((void**)&tL, g_t_lo);
    cudaGetSymbolAddress((void**)&w1H, g_w1_hi);
    cudaGetSymbolAddress((void**)&w1L, g_w1_lo);
    cudaGetSymbolAddress((void**)&w2H, g_w2_hi);
    cudaGetSymbolAddress((void**)&w2L, g_w2_lo);

    cudaFuncSetAttribute(gemm_tc, cudaFuncAttributeMaxDynamicSharedMemorySize, GEMM_SMEM_BYTES);

    // CSR build + weight prep
    zero_deg_kernel<<<(NN + 255) / 256, 256>>>();
    count_kernel<<<(EE + 255) / 256, 256>>>(ei);
    scan_kernel<<<1, 1024>>>();
    copy_cursor_kernel<<<(NN + 255) / 256, 256>>>();
    fill_kernel<<<(EE + 255) / 256, 256>>>(ei);
    prep_weights<<<(LL * DD * DD + 255) / 256, 256>>>(Ws1, Ws2);

    int gemm_grid = (NN + 127) / 128;   // 391

    const float* h = x;
    int hstride = DD;
    for (int i = 0; i < LL; i++) {
        aggregate_kernel<<<(NN * 32 + 255) / 256, 256>>>(h, hstride);
        // t = relu(agg @ W1 + b1) -> bf16 hi/lo
        gemm_tc<<<gemm_grid, 256, GEMM_SMEM_BYTES>>>(
            aggH, aggL, w1H + (long)i * DD * DD, w1L + (long)i * DD * DD,
            bs1 + (long)i * DD, nullptr, 0, tH, tL, NN, 0);
        // h = relu(t @ W2 + b2) -> fp32 node_embed slice
        gemm_tc<<<gemm_grid, 256, GEMM_SMEM_BYTES>>>(
            tH, tL, w2H + (long)i * DD * DD, w2L + (long)i * DD * DD,
            bs2 + (long)i * DD, node_out + (long)i * DD, LL * DD, nullptr, nullptr, NN, 1);
        h = node_out + (long)i * DD;
        hstride = LL * DD;
    }

    gstart_kernel<<<(GG + 1 + 255) / 256, 256>>>(batch);
    pool_kernel<<<GG, 256>>>(node_out, graph_out);
}

// round 15
// speedup vs baseline: 2.0961x; 1.3184x over previous
#include <cuda_runtime.h>
#include <cuda_bf16.h>
#include <cstdint>

#define NN 50000
#define EE 800000
#define DD 256
#define LL 3
#define GG 512

#if defined(__CUDA_ARCH_FEAT_SM103_ALL) || defined(__CUDA_ARCH_FEAT_SM100_ALL) || \
    defined(__CUDA_ARCH_FEAT_SM101_ALL) || defined(__CUDA_ARCH_SPECIFIC__)
#define HAS_TCGEN05 1
#else
#define HAS_TCGEN05 0
#endif

// ==================== PTX helpers (sm_103a-only) ====================
#if HAS_TCGEN05
__device__ __forceinline__ uint32_t smem_to_u32(const void* p) {
    uint32_t a;
    asm("{ .reg .u64 t; cvta.to.shared.u64 t, %1; cvt.u32.u64 %0, t; }" : "=r"(a) : "l"(p));
    return a;
}
__device__ __forceinline__ uint32_t elect_one_pred() {
    uint32_t pred;
    asm volatile("{\n\t.reg .pred p;\n\telect.sync _|p, 0xFFFFFFFF;\n\tselp.b32 %0, 1, 0, p;\n\t}" : "=r"(pred));
    return pred;
}
#define MBARRIER_INIT(addr, cnt) \
    asm volatile("mbarrier.init.shared.b64 [%0], %1;" :: "r"((uint32_t)(addr)), "r"((uint32_t)(cnt)) : "memory")
#define MBARRIER_WAIT_PARITY(mbar_smem_addr, phase_parity) do { \
    uint32_t _mbar = (uint32_t)(mbar_smem_addr); \
    uint32_t _parity = (uint32_t)(phase_parity); \
    uint32_t _done; \
    asm volatile("{\n\t.reg .pred p;\n\t" \
        "mbarrier.try_wait.parity.acquire.cta.shared::cta.b64 p, [%1], %2;\n\t" \
        "selp.b32 %0, 1, 0, p;\n\t}" \
        : "=r"(_done) : "r"(_mbar), "r"(_parity) : "memory"); \
    if (!_done) { \
        asm volatile("{\n\t.reg .pred P1;\n\t" \
            "WAIT_LOOP_%=:\n\t" \
            "mbarrier.try_wait.parity.acquire.cta.shared::cta.b64 P1, [%0], %1, 0x989680;\n\t" \
            "@P1 bra.uni WAIT_DONE_%=;\n\t" \
            "bra.uni WAIT_LOOP_%=;\n\t" \
            "WAIT_DONE_%=:\n\t}" \
            :: "r"(_mbar), "r"(_parity) : "memory"); \
    } \
} while(0)
#define TCGEN05_ALLOC(smem_result_addr, nCols) \
    asm volatile("tcgen05.alloc.cta_group::1.sync.aligned.shared::cta.b32 [%0], %1;" \
        :: "r"((uint32_t)(smem_result_addr)), "r"((uint32_t)(nCols)) : "memory")
#define TCGEN05_DEALLOC(tmem_addr, nCols) \
    asm volatile("tcgen05.dealloc.cta_group::1.sync.aligned.b32 %0, %1;" :: "r"(tmem_addr), "r"((uint32_t)(nCols)))
#define TCGEN05_RELINQUISH() \
    asm volatile("tcgen05.relinquish_alloc_permit.cta_group::1.sync.aligned;")
#define TCGEN05_COMMIT(mbar_smem_addr) \
    asm volatile("tcgen05.commit.cta_group::1.mbarrier::arrive::one.shared::cluster.b64 [%0];" \
        :: "r"((uint32_t)(mbar_smem_addr)) : "memory")
#define TCGEN05_WAIT_LD() asm volatile("tcgen05.wait::ld.sync.aligned;" ::: "memory")
#define TCGEN05_FENCE_AFTER() asm volatile("tcgen05.fence::after_thread_sync;" ::: "memory")
#define FENCE_PROXY_ASYNC_SHARED_CTA() asm volatile("fence.proxy.async.shared::cta;" ::: "memory")
#define TCGEN05_LD_32X32B_X32(r, tmem_addr) \
    asm volatile("tcgen05.ld.sync.aligned.32x32b.x32.b32 " \
        "{%0, %1, %2, %3, %4, %5, %6, %7, %8, %9, %10, %11, %12, %13, %14, %15, " \
        " %16, %17, %18, %19, %20, %21, %22, %23, %24, %25, %26, %27, %28, %29, %30, %31}, [%32];" \
        : "=r"((r)[0]),  "=r"((r)[1]),  "=r"((r)[2]),  "=r"((r)[3]), \
          "=r"((r)[4]),  "=r"((r)[5]),  "=r"((r)[6]),  "=r"((r)[7]), \
          "=r"((r)[8]),  "=r"((r)[9]),  "=r"((r)[10]), "=r"((r)[11]), \
          "=r"((r)[12]), "=r"((r)[13]), "=r"((r)[14]), "=r"((r)[15]), \
          "=r"((r)[16]), "=r"((r)[17]), "=r"((r)[18]), "=r"((r)[19]), \
          "=r"((r)[20]), "=r"((r)[21]), "=r"((r)[22]), "=r"((r)[23]), \
          "=r"((r)[24]), "=r"((r)[25]), "=r"((r)[26]), "=r"((r)[27]), \
          "=r"((r)[28]), "=r"((r)[29]), "=r"((r)[30]), "=r"((r)[31]) \
        : "r"(tmem_addr))

static constexpr uint64_t SMEM_DESC_BASE_SW128 =
    (uint64_t(2) << 61) | (uint64_t(1) << 46) | (uint64_t(64) << 32) | (uint64_t(1) << 16);
#define MAKE_SMEM_DESC(base_addr) (SMEM_DESC_BASE_SW128 | ((uint64_t)((base_addr) >> 4) & 0x3FFF))

__device__ __forceinline__ void mma_f16_ss(uint32_t d, uint64_t a, uint64_t b, uint32_t idesc, int en) {
    asm volatile("{\n\t.reg .pred p;\n\tsetp.ne.u32 p, %4, 0;\n\t"
        "tcgen05.mma.cta_group::1.kind::f16 [%0], %1, %2, %3, {%5, %5, %5, %5}, p;\n\t}"
        :: "r"(d), "l"(a), "l"(b), "r"(idesc), "r"((uint32_t)en), "r"(0u) : "memory");
}

// idesc: dtype F32 (1<<4), atype BF16 (1<<7), btype BF16 (1<<10), N=256 (32<<17), M=128 (8<<24)
static constexpr uint32_t GEMM_IDESC =
    (1u << 4) | (1u << 7) | (1u << 10) | ((256u / 8) << 17) | ((128u / 16) << 24);
#endif // HAS_TCGEN05

#define SMEM_SWIZZLE_128B(byte_offset) ((byte_offset) ^ (((byte_offset) >> 3) & 0x70))

// ==================== scratch ====================
__device__ __align__(256) __nv_bfloat16 g_agg_hi[NN * DD];
__device__ __align__(256) __nv_bfloat16 g_agg_lo[NN * DD];
__device__ __align__(256) __nv_bfloat16 g_w1_hi[LL * DD * DD];   // transposed [l][n][k]
__device__ __align__(256) __nv_bfloat16 g_w1_lo[LL * DD * DD];
__device__ __align__(256) __nv_bfloat16 g_w2_hi[LL * DD * DD];
__device__ __align__(256) __nv_bfloat16 g_w2_lo[LL * DD * DD];
__device__ int g_deg[NN];
__device__ int g_cursor[NN];
__device__ int g_rowstart[NN + 1];
__device__ int g_esrc[EE];
__device__ int g_gstart[GG + 1];

// ==================== CSR build ====================
__global__ void count_kernel(const int* __restrict__ ei) {
    int e = blockIdx.x * blockDim.x + threadIdx.x;
    if (e < EE) atomicAdd(&g_deg[ei[EE + e]], 1);
}
__global__ void scan_kernel() {
    __shared__ int partials[1024];
    const int n = NN;
    int tid = threadIdx.x;
    int chunk = (n + 1023) / 1024;
    int beg = tid * chunk;
    int end = beg + chunk; if (end > n) end = n;
    int sum = 0;
    for (int i = beg; i < end; i++) sum += g_deg[i];
    partials[tid] = sum;
    __syncthreads();
    for (int off = 1; off < 1024; off <<= 1) {
        int v = 0;
        if (tid >= off) v = partials[tid - off];
        __syncthreads();
        partials[tid] += v;
        __syncthreads();
    }
    int run = (tid == 0) ? 0 : partials[tid - 1];
    for (int i = beg; i < end; i++) { g_rowstart[i] = run; run += g_deg[i]; }
    if (tid == 0) g_rowstart[n] = EE;
}
__global__ void fill_kernel(const int* __restrict__ ei) {
    int e = blockIdx.x * blockDim.x + threadIdx.x;
    if (e < EE) {
        int dst = ei[EE + e];
        int pos = atomicAdd(&g_cursor[dst], 1);
        g_esrc[pos] = ei[e];
    }
}

// ==================== weight prep: transpose + bf16 split ====================
__global__ void prep_weights(const float* __restrict__ Ws1, const float* __restrict__ Ws2) {
    int i = blockIdx.x * blockDim.x + threadIdx.x;
    if (i >= LL * DD * DD) return;
    int l = i >> 16;
    int r = i & 65535;
    int n = r >> 8;
    int k = r & 255;
    float w1 = Ws1[l * 65536 + k * 256 + n];
    __nv_bfloat16 h1 = __float2bfloat16(w1);
    g_w1_hi[i] = h1;
    g_w1_lo[i] = __float2bfloat16(w1 - __bfloat162float(h1));
    float w2 = Ws2[l * 65536 + k * 256 + n];
    __nv_bfloat16 h2 = __float2bfloat16(w2);
    g_w2_hi[i] = h2;
    g_w2_lo[i] = __float2bfloat16(w2 - __bfloat162float(h2));
}

// ==================== aggregation -> bf16 hi/lo ====================
__device__ __forceinline__ uint32_t pack_hi2(float a, float b, uint32_t& lo_out) {
    __nv_bfloat16 ha = __float2bfloat16(a);
    __nv_bfloat16 hb = __float2bfloat16(b);
    __nv_bfloat16 la = __float2bfloat16(a - __bfloat162float(ha));
    __nv_bfloat16 lb = __float2bfloat16(b - __bfloat162float(hb));
    lo_out = (uint32_t)__bfloat16_as_ushort(la) | ((uint32_t)__bfloat16_as_ushort(lb) << 16);
    return (uint32_t)__bfloat16_as_ushort(ha) | ((uint32_t)__bfloat16_as_ushort(hb) << 16);
}

__global__ __launch_bounds__(256) void aggregate_kernel(const float* __restrict__ h, int hstride) {
    int node = (blockIdx.x * blockDim.x + threadIdx.x) >> 5;
    if (node >= NN) return;
    int lane = threadIdx.x & 31;
    int beg = g_rowstart[node];
    int end = g_rowstart[node + 1];
    int d0 = lane * 4;
    int d1 = 128 + lane * 4;
    float4 acc0 = make_float4(0.f, 0.f, 0.f, 0.f);
    float4 acc1 = make_float4(0.f, 0.f, 0.f, 0.f);
    for (int e = beg; e < end; e++) {
        int s = __ldg(&g_esrc[e]);
        const float* hs = h + (long)s * hstride;
        float4 a = *(const float4*)(hs + d0);
        float4 b = *(const float4*)(hs + d1);
        acc0.x += a.x; acc0.y += a.y; acc0.z += a.z; acc0.w += a.w;
        acc1.x += b.x; acc1.y += b.y; acc1.z += b.z; acc1.w += b.w;
    }
    const float* hn = h + (long)node * hstride;
    float4 a = *(const float4*)(hn + d0);
    float4 b = *(const float4*)(hn + d1);
    acc0.x += a.x; acc0.y += a.y; acc0.z += a.z; acc0.w += a.w;
    acc1.x += b.x; acc1.y += b.y; acc1.z += b.z; acc1.w += b.w;

    uint32_t l01, l23, m01, m23;
    uint32_t h01 = pack_hi2(acc0.x, acc0.y, l01);
    uint32_t h23 = pack_hi2(acc0.z, acc0.w, l23);
    uint32_t i01 = pack_hi2(acc1.x, acc1.y, m01);
    uint32_t i23 = pack_hi2(acc1.z, acc1.w, m23);
    __nv_bfloat16* oh = g_agg_hi + (long)node * DD;
    __nv_bfloat16* ol = g_agg_lo + (long)node * DD;
    *(uint2*)(oh + d0) = make_uint2(h01, h23);
    *(uint2*)(ol + d0) = make_uint2(l01, l23);
    *(uint2*)(oh + d1) = make_uint2(i01, i23);
    *(uint2*)(ol + d1) = make_uint2(m01, m23);
}

// ==================== fused MLP: out = relu(relu(A@W1+b1)@W2+b2) ====================
// Phase 1: D1(TMEM cols 0-255)   = A(agg hi/lo from gmem) @ W1 (3-way bf16 split)
// Epi 1:   t = relu(D1+b1) -> bf16 hi/lo -> SMEM (4 SW128 chunks [128x64])
// Phase 2: D2(TMEM cols 256-511) = t(SMEM) @ W2 (3-way split, W2 chunks streamed)
// Epi 2:   out = relu(D2+b2) -> fp32 gmem (stride ldc)
// mbar usage (2 barriers, 4 commits each across both phases; all wait parities unique):
//   phase1 chunk c -> mbar[c&1]; c>=2 waits mbar[c&1]@0; epi1 waits mbar1@1
//   phase2 chunk c -> mbar[c&1]; c=1 waits mbar0@0, c=2 waits mbar1@0, c=3 waits mbar0@1
//   epi2 waits mbar1@1
#define REL_TM     0
#define REL_MBAR0  8
#define REL_MBAR1  16
#define STG_BASE   1024
#define STG_BYTES  98304          // AH 16K + AL 16K + BH 32K + BL 32K
#define OFF_AH     0
#define OFF_AL     16384
#define OFF_BH     32768
#define OFF_BL     65536
// Phase-2 overlay (reuses phase-1 stages; valid after epi1 wait):
#define OFF_A2H    0              // 4 chunks x 16KB = 64KB at STG_BASE
#define OFF_A2L    65536          // 64KB
#define OFF_W2H    131072         // 32KB
#define OFF_W2L    163840         // 32KB
#define MLP_SMEM_BYTES (STG_BASE + 2 * STG_BYTES + 1024)   // 197.6KB

__global__ __launch_bounds__(256, 1) __cluster_dims__(1, 1, 1)
void mlp_tc(const __nv_bfloat16* __restrict__ Ahi, const __nv_bfloat16* __restrict__ Alo,
            const __nv_bfloat16* __restrict__ W1hi, const __nv_bfloat16* __restrict__ W1lo,
            const float* __restrict__ b1,
            const __nv_bfloat16* __restrict__ W2hi, const __nv_bfloat16* __restrict__ W2lo,
            const float* __restrict__ b2,
            float* __restrict__ outF, int ldc, int M)
{
#if HAS_TCGEN05
    extern __shared__ char smem_raw[];
    uint32_t sraw = smem_to_u32(smem_raw);
    uint32_t sb = (sraw + 1023u) & ~1023u;
    char* smem = smem_raw + (sb - sraw);

    int tid = threadIdx.x;
    int rowBase = blockIdx.x * 128;
    int wg = tid >> 7;
    int wr = tid & 127;
    int m = rowBase + wr;
    int colWG = wg << 7;

    if (tid < 32) {
        TCGEN05_ALLOC(sb + REL_TM, 512);
        TCGEN05_RELINQUISH();
    }
    if (tid == 0) {
        MBARRIER_INIT(sb + REL_MBAR0, 1);
        MBARRIER_INIT(sb + REL_MBAR1, 1);
    }
    __syncthreads();
    uint32_t tm;
    asm volatile("ld.shared.b32 %0, [%1];" : "=r"(tm) : "r"(sb + REL_TM));

    // ---------- Phase 1: A @ W1 -> D1 (cols 0-255), double-buffered ----------
    for (int c = 0; c < 4; c++) {
        int st = c & 1;
        uint32_t stage = sb + STG_BASE + (uint32_t)st * STG_BYTES;
        char* sm = smem + STG_BASE + st * STG_BYTES;
        uint32_t mbar = sb + (st ? REL_MBAR1 : REL_MBAR0);
        int k0 = c * 64;

        if (c >= 2) MBARRIER_WAIT_PARITY(mbar, 0);

        for (int i = tid; i < 128 * 8; i += 256) {
            int r = i >> 3, q = i & 7;
            uint32_t sw = SMEM_SWIZZLE_128B((uint32_t)(r * 128 + q * 16));
            uint4 vh = make_uint4(0, 0, 0, 0), vl = make_uint4(0, 0, 0, 0);
            int gr = rowBase + r;
            if (gr < M) {
                vh = *(const uint4*)(Ahi + (size_t)gr * 256 + k0 + q * 8);
                vl = *(const uint4*)(Alo + (size_t)gr * 256 + k0 + q * 8);
            }
            *(uint4*)(sm + OFF_AH + sw) = vh;
            *(uint4*)(sm + OFF_AL + sw) = vl;
        }
        for (int i = tid; i < 256 * 8; i += 256) {
            int n = i >> 3, q = i & 7;
            uint32_t sw = SMEM_SWIZZLE_128B((uint32_t)(n * 128 + q * 16));
            *(uint4*)(sm + OFF_BH + sw) = *(const uint4*)(W1hi + (size_t)n * 256 + k0 + q * 8);
            *(uint4*)(sm + OFF_BL + sw) = *(const uint4*)(W1lo + (size_t)n * 256 + k0 + q * 8);
        }
        FENCE_PROXY_ASYNC_SHARED_CTA();
        __syncthreads();

        if (tid < 32 && elect_one_pred()) {
            uint64_t dAH = MAKE_SMEM_DESC(stage + OFF_AH);
            uint64_t dAL = MAKE_SMEM_DESC(stage + OFF_AL);
            uint64_t dBH = MAKE_SMEM_DESC(stage + OFF_BH);
            uint64_t dBL = MAKE_SMEM_DESC(stage + OFF_BL);
            #pragma unroll
            for (int s = 0; s < 4; s++) {
                uint64_t off = (uint64_t)(2 * s);
                mma_f16_ss(tm, dAH + off, dBH + off, GEMM_IDESC, !(c == 0 && s == 0));
                mma_f16_ss(tm, dAL + off, dBH + off, GEMM_IDESC, 1);
                mma_f16_ss(tm, dAH + off, dBL + off, GEMM_IDESC, 1);
            }
            TCGEN05_COMMIT(mbar);
        }
    }

    // ---------- Epilogue 1: t = relu(D1+b1) -> bf16 split -> SMEM A2 ----------
    MBARRIER_WAIT_PARITY(sb + REL_MBAR1, 1);   // all phase-1 MMAs done
    TCGEN05_FENCE_AFTER();
    __syncthreads();                            // everyone past phase-1 stage use
    for (int c = 0; c < 4; c++) {
        uint32_t d[32];
        TCGEN05_LD_32X32B_X32(d, tm + colWG + c * 32);
        TCGEN05_WAIT_LD();
        int col0 = colWG + c * 32;              // global col of first reg
        int kc = col0 >> 6;                     // phase-2 k-chunk (0..3)
        int ic = col0 & 63;                     // col within chunk
        char* a2h = smem + STG_BASE + OFF_A2H + kc * 16384;
        char* a2l = smem + STG_BASE + OFF_A2L + kc * 16384;
        #pragma unroll
        for (int j = 0; j < 16; j++) {
            float v0 = fmaxf(__uint_as_float(d[2 * j]) + __ldg(&b1[col0 + 2 * j]), 0.f);
            float v1 = fmaxf(__uint_as_float(d[2 * j + 1]) + __ldg(&b1[col0 + 2 * j + 1]), 0.f);
            uint32_t pl;
            uint32_t ph = pack_hi2(v0, v1, pl);
            uint32_t byte = (uint32_t)(wr * 128 + (ic + 2 * j) * 2);
            uint32_t sw = SMEM_SWIZZLE_128B(byte);
            *(uint32_t*)(a2h + sw) = ph;
            *(uint32_t*)(a2l + sw) = pl;
        }
    }
    FENCE_PROXY_ASYNC_SHARED_CTA();
    __syncthreads();

    // ---------- Phase 2: t @ W2 -> D2 (cols 256-511), W2 single-buffered ----------
    {
        uint32_t a2hB = sb + STG_BASE + OFF_A2H;
        uint32_t a2lB = sb + STG_BASE + OFF_A2L;
        char* w2h = smem + STG_BASE + OFF_W2H;
        char* w2l = smem + STG_BASE + OFF_W2L;
        uint32_t w2hA = sb + STG_BASE + OFF_W2H;
        uint32_t w2lA = sb + STG_BASE + OFF_W2L;

        for (int c = 0; c < 4; c++) {
            int k0 = c * 64;
            // wait for previous chunk's MMA before overwriting W2 stage
            if (c == 1) MBARRIER_WAIT_PARITY(sb + REL_MBAR0, 0);
            if (c == 2) MBARRIER_WAIT_PARITY(sb + REL_MBAR1, 0);
            if (c == 3) MBARRIER_WAIT_PARITY(sb + REL_MBAR0, 1);

            for (int i = tid; i < 256 * 8; i += 256) {
                int n = i >> 3, q = i & 7;
                uint32_t sw = SMEM_SWIZZLE_128B((uint32_t)(n * 128 + q * 16));
                *(uint4*)(w2h + sw) = *(const uint4*)(W2hi + (size_t)n * 256 + k0 + q * 8);
                *(uint4*)(w2l + sw) = *(const uint4*)(W2lo + (size_t)n * 256 + k0 + q * 8);
            }
            FENCE_PROXY_ASYNC_SHARED_CTA();
            __syncthreads();

            if (tid < 32 && elect_one_pred()) {
                uint64_t dAH = MAKE_SMEM_DESC(a2hB + (uint32_t)c * 16384);
                uint64_t dAL = MAKE_SMEM_DESC(a2lB + (uint32_t)c * 16384);
                uint64_t dBH = MAKE_SMEM_DESC(w2hA);
                uint64_t dBL = MAKE_SMEM_DESC(w2lA);
                #pragma unroll
                for (int s = 0; s < 4; s++) {
                    uint64_t off = (uint64_t)(2 * s);
                    mma_f16_ss(tm + 256, dAH + off, dBH + off, GEMM_IDESC, !(c == 0 && s == 0));
                    mma_f16_ss(tm + 256, dAL + off, dBH + off, GEMM_IDESC, 1);
                    mma_f16_ss(tm + 256, dAH + off, dBL + off, GEMM_IDESC, 1);
                }
                TCGEN05_COMMIT(sb + ((c & 1) ? REL_MBAR1 : REL_MBAR0));
            }
        }
    }

    // ---------- Epilogue 2: out = relu(D2+b2) -> fp32 ----------
    MBARRIER_WAIT_PARITY(sb + REL_MBAR1, 1);   // phase-2 chunk 3 commit
    TCGEN05_FENCE_AFTER();
    for (int c = 0; c < 4; c++) {
        uint32_t d[32];
        TCGEN05_LD_32X32B_X32(d, tm + 256 + colWG + c * 32);
        TCGEN05_WAIT_LD();
        int col0 = colWG + c * 32;
        if (m < M) {
            float* o = outF + (size_t)m * ldc + col0;
            #pragma unroll
            for (int j = 0; j < 8; j++) {
                float4 v;
                v.x = fmaxf(__uint_as_float(d[4 * j + 0]) + __ldg(&b2[col0 + 4 * j + 0]), 0.f);
                v.y = fmaxf(__uint_as_float(d[4 * j + 1]) + __ldg(&b2[col0 + 4 * j + 1]), 0.f);
                v.z = fmaxf(__uint_as_float(d[4 * j + 2]) + __ldg(&b2[col0 + 4 * j + 2]), 0.f);
                v.w = fmaxf(__uint_as_float(d[4 * j + 3]) + __ldg(&b2[col0 + 4 * j + 3]), 0.f);
                *(float4*)(o + 4 * j) = v;
            }
        }
    }
    __syncthreads();
    if (tid < 32) TCGEN05_DEALLOC(tm, 512);
#else
    // Fallback for the non-'a' PTX pass (never executed at runtime).
    int tid = threadIdx.x;
    int rowBase = blockIdx.x * 128;
    int m = rowBase + tid;          // threads 0-127 handle rows; 128-255 idle
    if (tid < 128 && m < M) {
        float t[256];
        for (int n = 0; n < 256; n++) {
            float acc = 0.f;
            for (int k = 0; k < 256; k++) {
                float av = __bfloat162float(Ahi[(size_t)m * 256 + k]) +
                           __bfloat162float(Alo[(size_t)m * 256 + k]);
                float bv = __bfloat162float(W1hi[(size_t)n * 256 + k]) +
                           __bfloat162float(W1lo[(size_t)n * 256 + k]);
                acc += av * bv;
            }
            float tv = fmaxf(acc + b1[n], 0.f);
            __nv_bfloat16 hh = __float2bfloat16(tv);
            t[n] = __bfloat162float(hh) + __bfloat162float(__float2bfloat16(tv - __bfloat162float(hh)));
        }
        for (int n = 0; n < 256; n++) {
            float acc = 0.f;
            for (int k = 0; k < 256; k++) {
                float bv = __bfloat162float(W2hi[(size_t)n * 256 + k]) +
                           __bfloat162float(W2lo[(size_t)n * 256 + k]);
                acc += t[k] * bv;
            }
            outF[(size_t)m * ldc + n] = fmaxf(acc + b2[n], 0.f);
        }
    }
#endif
}

// ==================== pooling ====================
__global__ void gstart_kernel(const int* __restrict__ batch) {
    int g = blockIdx.x * blockDim.x + threadIdx.x;
    if (g > GG) return;
    int lo = 0, hi = NN;
    while (lo < hi) {
        int mid = (lo + hi) >> 1;
        if (batch[mid] < g) lo = mid + 1; else hi = mid;
    }
    g_gstart[g] = lo;
}
__global__ __launch_bounds__(256) void pool_kernel(
    const float* __restrict__ node_embed, float* __restrict__ graph_out)
{
    int g = blockIdx.x;
    int beg = g_gstart[g];
    int end = g_gstart[g + 1];
    int cnt = end - beg; if (cnt < 1) cnt = 1;
    float inv = 1.0f / (float)cnt;
    for (int d = threadIdx.x; d < LL * DD; d += blockDim.x) {
        float s = 0.f;
        for (int n = beg; n < end; n++) s += node_embed[(long)n * (LL * DD) + d];
        graph_out[(long)g * (LL * DD) + d] = s * inv;
    }
}

// ==================== launch ====================
extern "C" void kernel_launch(void* const* d_in, const int* in_sizes, int n_in,
                              void* d_out, int out_size)
{
    const float* x     = (const float*)d_in[0];
    const int*   ei    = (const int*)d_in[1];
    const int*   batch = (const int*)d_in[2];
    const float* Ws1   = (const float*)d_in[3];
    const float* bs1   = (const float*)d_in[4];
    const float* Ws2   = (const float*)d_in[5];
    const float* bs2   = (const float*)d_in[6];

    float* out       = (float*)d_out;
    float* graph_out = out;
    float* node_out  = out + (long)GG * LL * DD;

    __nv_bfloat16 *aggH, *aggL, *w1H, *w1L, *w2H, *w2L;
    int *degP, *curP, *rowP;
    cudaGetSymbolAddress((void**)&aggH, g_agg_hi);
    cudaGetSymbolAddress((void**)&aggL, g_agg_lo);
    cudaGetSymbolAddress((void**)&w1H, g_w1_hi);
    cudaGetSymbolAddress((void**)&w1L, g_w1_lo);
    cudaGetSymbolAddress((void**)&w2H, g_w2_hi);
    cudaGetSymbolAddress((void**)&w2L, g_w2_lo);
    cudaGetSymbolAddress((void**)&degP, g_deg);
    cudaGetSymbolAddress((void**)&curP, g_cursor);
    cudaGetSymbolAddress((void**)&rowP, g_rowstart);

    cudaFuncSetAttribute(mlp_tc, cudaFuncAttributeMaxDynamicSharedMemorySize, MLP_SMEM_BYTES);

    // CSR build + weight prep (memset/memcpy replace two trivial kernels)
    cudaMemsetAsync(degP, 0, NN * sizeof(int));
    count_kernel<<<(EE + 255) / 256, 256>>>(ei);
    scan_kernel<<<1, 1024>>>();
    cudaMemcpyAsync(curP, rowP, NN * sizeof(int), cudaMemcpyDeviceToDevice);
    fill_kernel<<<(EE + 255) / 256, 256>>>(ei);
    prep_weights<<<(LL * DD * DD + 255) / 256, 256>>>(Ws1, Ws2);

    int mlp_grid = (NN + 127) / 128;   // 391

    const float* h = x;
    int hstride = DD;
    for (int i = 0; i < LL; i++) {
        aggregate_kernel<<<(NN * 32 + 255) / 256, 256>>>(h, hstride);
        mlp_tc<<<mlp_grid, 256, MLP_SMEM_BYTES>>>(
            aggH, aggL,
            w1H + (long)i * DD * DD, w1L + (long)i * DD * DD, bs1 + (long)i * DD,
            w2H + (long)i * DD * DD, w2L + (long)i * DD * DD, bs2 + (long)i * DD,
            node_out + (long)i * DD, LL * DD, NN);
        h = node_out + (long)i * DD;
        hstride = LL * DD;
    }

    gstart_kernel<<<(GG + 1 + 255) / 256, 256>>>(batch);
    pool_kernel<<<GG, 256>>>(node_out, graph_out);
}